// round 2
// baseline (speedup 1.0000x reference)
#include <cuda_runtime.h>

// out[b, f] = x0[b, f] * dot(x[b,:], w) + bias[f] + x[b, f]
// B = 16384 rows, F = 2048 cols, fp32. One CTA per row, 256 threads,
// each thread owns 8 columns (2 x float4).
//
// R2 changes vs R1:
//  - ALL four streams (x, w, x0, bias) loaded up-front -> 4 in-flight
//    LDG.128 per thread (double the outstanding DRAM bytes), no
//    post-barrier DRAM round-trip.
//  - pa = bias + x computed BEFORE the barrier (independent of the dot),
//    so only x0 + pa registers are live across the sync.
//  - Single __syncthreads: every thread sums the 8 warp partials from
//    shared memory (broadcast LDS) instead of a second barrier.

#define F_DIM 2048
#define VEC_PER_ROW (F_DIM / 4)   // 512 float4
#define THREADS 256
#define NWARPS (THREADS / 32)

__global__ __launch_bounds__(THREADS)
void cross_fused_kernel(const float4* __restrict__ x0,
                        const float4* __restrict__ x,
                        const float4* __restrict__ w,
                        const float4* __restrict__ bias,
                        float4* __restrict__ out)
{
    const int row = blockIdx.x;
    const int tid = threadIdx.x;
    const long base = (long)row * VEC_PER_ROW;

    const int i0 = tid;
    const int i1 = tid + THREADS;

    // Front-batched loads: maximize outstanding DRAM requests per warp.
    float4 xa  = x[base + i0];
    float4 xb  = x[base + i1];
    float4 x0a = x0[base + i0];
    float4 x0b = x0[base + i1];
    float4 wa  = w[i0];
    float4 wb  = w[i1];
    float4 ba  = bias[i0];
    float4 bb  = bias[i1];

    // Per-thread partial dot.
    float s = xa.x * wa.x + xa.y * wa.y + xa.z * wa.z + xa.w * wa.w
            + xb.x * wb.x + xb.y * wb.y + xb.z * wb.z + xb.w * wb.w;

    // Precompute (bias + x) before the barrier; x/w/bias regs die here.
    float4 pa, pb;
    pa.x = ba.x + xa.x;  pa.y = ba.y + xa.y;
    pa.z = ba.z + xa.z;  pa.w = ba.w + xa.w;
    pb.x = bb.x + xb.x;  pb.y = bb.y + xb.y;
    pb.z = bb.z + xb.z;  pb.w = bb.w + xb.w;

    // Warp reduce.
    #pragma unroll
    for (int off = 16; off > 0; off >>= 1)
        s += __shfl_xor_sync(0xFFFFFFFFu, s, off);

    // Single-barrier cross-warp reduce: lane 0 publishes, everyone sums.
    __shared__ float warp_sums[NWARPS];
    const int lane = tid & 31;
    const int warp = tid >> 5;
    if (lane == 0) warp_sums[warp] = s;
    __syncthreads();

    float xw = 0.0f;
    #pragma unroll
    for (int i = 0; i < NWARPS; i++)
        xw += warp_sums[i];   // broadcast LDS, conflict-free

    // out = x0 * xw + (bias + x)
    float4 oa, ob;
    oa.x = fmaf(x0a.x, xw, pa.x);
    oa.y = fmaf(x0a.y, xw, pa.y);
    oa.z = fmaf(x0a.z, xw, pa.z);
    oa.w = fmaf(x0a.w, xw, pa.w);
    ob.x = fmaf(x0b.x, xw, pb.x);
    ob.y = fmaf(x0b.y, xw, pb.y);
    ob.z = fmaf(x0b.z, xw, pb.z);
    ob.w = fmaf(x0b.w, xw, pb.w);

    out[base + i0] = oa;
    out[base + i1] = ob;
}

extern "C" void kernel_launch(void* const* d_in, const int* in_sizes, int n_in,
                              void* d_out, int out_size)
{
    const float4* x0   = (const float4*)d_in[0];
    const float4* x    = (const float4*)d_in[1];
    const float4* w    = (const float4*)d_in[2];
    const float4* bias = (const float4*)d_in[3];
    float4* out = (float4*)d_out;

    const int rows = in_sizes[0] / F_DIM;  // 16384
    cross_fused_kernel<<<rows, THREADS>>>(x0, x, w, bias, out);
}

// round 3
// speedup vs baseline: 1.0068x; 1.0068x over previous
#include <cuda_runtime.h>

// out[b, f] = x0[b, f] * dot(x[b,:], w) + bias[f] + x[b, f]
// B = 16384 rows, F = 2048 cols, fp32. One CTA per row, 256 threads,
// each thread owns 8 columns (2 x float4).
//
// R3 changes vs R2:
//  - __ldcs (evict-first) on the single-use x / x0 streams, __stcs on the
//    single-use out stream: stops 384 MiB of dead data from churning L2
//    and interfering between the read and write streams.
//  - w / bias stay default-cached (reused by all 16384 CTAs -> L2-resident).

#define F_DIM 2048
#define VEC_PER_ROW (F_DIM / 4)   // 512 float4
#define THREADS 256
#define NWARPS (THREADS / 32)

__global__ __launch_bounds__(THREADS)
void cross_fused_kernel(const float4* __restrict__ x0,
                        const float4* __restrict__ x,
                        const float4* __restrict__ w,
                        const float4* __restrict__ bias,
                        float4* __restrict__ out)
{
    const int row = blockIdx.x;
    const int tid = threadIdx.x;
    const long base = (long)row * VEC_PER_ROW;

    const int i0 = tid;
    const int i1 = tid + THREADS;

    // Front-batched loads; streaming (evict-first) policy on the big
    // single-use streams.
    float4 xa  = __ldcs(&x[base + i0]);
    float4 xb  = __ldcs(&x[base + i1]);
    float4 x0a = __ldcs(&x0[base + i0]);
    float4 x0b = __ldcs(&x0[base + i1]);
    float4 wa  = w[i0];
    float4 wb  = w[i1];
    float4 ba  = bias[i0];
    float4 bb  = bias[i1];

    // Per-thread partial dot.
    float s = xa.x * wa.x + xa.y * wa.y + xa.z * wa.z + xa.w * wa.w
            + xb.x * wb.x + xb.y * wb.y + xb.z * wb.z + xb.w * wb.w;

    // Precompute (bias + x) before the barrier; x/w/bias regs die here.
    float4 pa, pb;
    pa.x = ba.x + xa.x;  pa.y = ba.y + xa.y;
    pa.z = ba.z + xa.z;  pa.w = ba.w + xa.w;
    pb.x = bb.x + xb.x;  pb.y = bb.y + xb.y;
    pb.z = bb.z + xb.z;  pb.w = bb.w + xb.w;

    // Warp reduce.
    #pragma unroll
    for (int off = 16; off > 0; off >>= 1)
        s += __shfl_xor_sync(0xFFFFFFFFu, s, off);

    // Single-barrier cross-warp reduce: lane 0 publishes, everyone sums.
    __shared__ float warp_sums[NWARPS];
    const int lane = tid & 31;
    const int warp = tid >> 5;
    if (lane == 0) warp_sums[warp] = s;
    __syncthreads();

    float xw = 0.0f;
    #pragma unroll
    for (int i = 0; i < NWARPS; i++)
        xw += warp_sums[i];   // broadcast LDS, conflict-free

    // out = x0 * xw + (bias + x), streaming store.
    float4 oa, ob;
    oa.x = fmaf(x0a.x, xw, pa.x);
    oa.y = fmaf(x0a.y, xw, pa.y);
    oa.z = fmaf(x0a.z, xw, pa.z);
    oa.w = fmaf(x0a.w, xw, pa.w);
    ob.x = fmaf(x0b.x, xw, pb.x);
    ob.y = fmaf(x0b.y, xw, pb.y);
    ob.z = fmaf(x0b.z, xw, pb.z);
    ob.w = fmaf(x0b.w, xw, pb.w);

    __stcs(&out[base + i0], oa);
    __stcs(&out[base + i1], ob);
}

extern "C" void kernel_launch(void* const* d_in, const int* in_sizes, int n_in,
                              void* d_out, int out_size)
{
    const float4* x0   = (const float4*)d_in[0];
    const float4* x    = (const float4*)d_in[1];
    const float4* w    = (const float4*)d_in[2];
    const float4* bias = (const float4*)d_in[3];
    float4* out = (float4*)d_out;

    const int rows = in_sizes[0] / F_DIM;  // 16384
    cross_fused_kernel<<<rows, THREADS>>>(x0, x, w, bias, out);
}